// round 14
// baseline (speedup 1.0000x reference)
#include <cuda_runtime.h>
#include <cuda_bf16.h>
#include <cstdint>

#define HW   2304
#define CIN  256
#define CMID 16
#define NB   4
#define ROWS 16                                   // rows == pixels per block
#define BLOCKS_PER_BATCH (HW / ROWS)              // 144
#define NBLOCKS (BLOCKS_PER_BATCH * NB)           // 576
#define PAIR_BYTES (2 * HW * 4)                   // 18432
#define NSLOT 2

// Scratch / barrier state (static device globals — no allocations)
__device__ float g_part[NB][BLOCKS_PER_BATCH][2];
__device__ unsigned g_cnt   = 0;
__device__ unsigned g_epoch = 0;

// ---------------------------------------------------------------------------
// Fused kernel. Phase A: this block's 16 pixels through 256->16 GEMM, tanh,
// 16->2 projections (v, mean offsets kept in SMEM). Publish partial sums.
// Grid barrier (all 576 blocks resident by construction). Phase B: reduce
// partials, params, mean/det writes, separable exps, pipelined TMA stores.
// ---------------------------------------------------------------------------
__global__ __launch_bounds__(288, 4) void fused(
    const float* __restrict__ x,
    const float* __restrict__ map_w,  const float* __restrict__ map_b,
    const float* __restrict__ mean_w, const float* __restrict__ mean_b,
    const float* __restrict__ cov_w,  const float* __restrict__ cov_b,
    float* __restrict__ out_pdf, float* __restrict__ out_mean,
    float* __restrict__ out_det)
{
    __shared__ __align__(16) float ring[NSLOT][2 * HW];   // 36 KB (phase A: weights)
    __shared__ __align__(16) float ex[ROWS][48];
    __shared__ float ey[ROWS][48];
    __shared__ float prm[ROWS][5];
    __shared__ float vloc[ROWS][2], moloc[ROWS][2];
    __shared__ float ss[8][2];

    const int bx   = blockIdx.x;
    const int b    = blockIdx.y;
    const int i0   = bx * ROWS;
    const int tid  = threadIdx.x;
    const int warp = tid >> 5;            // 0..8
    const int lane = tid & 31;

    float* sw = (float*)ring;             // alias: weights live here in phase A

    // ---- Phase A -----------------------------------------------------------
    // issue this warp's x loads first (2 pixels, first K-half)
    float4 xv0[2], xv1[2];
    const int pix0 = i0 + warp * 2;
    const float* xb = x + ((long)b * HW + pix0) * CIN;
    if (warp < 8) {
        #pragma unroll
        for (int p = 0; p < 2; ++p)
            xv0[p] = ((const float4*)(xb + p * CIN))[lane];
    }
    // stage weights into ring space (1024 float4 over 288 threads)
    {
        const float4* src = (const float4*)map_w;
        float4* dst = (float4*)sw;
        for (int i = tid; i < (CMID * CIN) / 4; i += 288) dst[i] = src[i];
    }
    __syncthreads();

    if (warp < 8) {
        const float4* sw4 = (const float4*)sw;
        float acc[2][CMID];
        // pass 1: first K-half
        #pragma unroll
        for (int c = 0; c < CMID; ++c) {
            const float4 w0 = sw4[c * 64 + lane];
            #pragma unroll
            for (int p = 0; p < 2; ++p) {
                float a;
                a = xv0[p].x * w0.x;
                a = fmaf(xv0[p].y, w0.y, a);
                a = fmaf(xv0[p].z, w0.z, a);
                a = fmaf(xv0[p].w, w0.w, a);
                acc[p][c] = a;
            }
        }
        // load second K-half, pass 2
        #pragma unroll
        for (int p = 0; p < 2; ++p)
            xv1[p] = ((const float4*)(xb + p * CIN))[lane + 32];
        #pragma unroll
        for (int c = 0; c < CMID; ++c) {
            const float4 w1 = sw4[c * 64 + 32 + lane];
            #pragma unroll
            for (int p = 0; p < 2; ++p) {
                float a = acc[p][c];
                a = fmaf(xv1[p].x, w1.x, a);
                a = fmaf(xv1[p].y, w1.y, a);
                a = fmaf(xv1[p].z, w1.z, a);
                a = fmaf(xv1[p].w, w1.w, a);
                acc[p][c] = a;
            }
        }

        // Halving butterfly: 16 accs -> 1 per lane per 16-lane half
        #pragma unroll
        for (int st = 0; st < 4; ++st) {
            const int off = 1 << st;
            const bool up = (lane >> st) & 1;
            const int half = 8 >> st;
            #pragma unroll
            for (int p = 0; p < 2; ++p) {
                #pragma unroll
                for (int i = 0; i < 8; ++i) {
                    if (i < half) {
                        float send  = up ? acc[p][i] : acc[p][i + half];
                        float other = __shfl_xor_sync(0xffffffffu, send, off);
                        float keep  = up ? acc[p][i + half] : acc[p][i];
                        acc[p][i] = keep + other;
                    }
                }
            }
        }
        #pragma unroll
        for (int p = 0; p < 2; ++p)
            acc[p][0] += __shfl_xor_sync(0xffffffffu, acc[p][0], 16);

        const int ch = ((lane & 1) << 3) | ((lane & 2) << 1)
                     | ((lane & 4) >> 1) | ((lane & 8) >> 3);
        const float mb  = __ldg(&map_b[ch]);
        const float wm0 = __ldg(&mean_w[ch]);
        const float wm1 = __ldg(&mean_w[CMID + ch]);
        const float wc0 = __ldg(&cov_w[ch]);
        const float wc1 = __ldg(&cov_w[CMID + ch]);
        const float mb0 = __ldg(&mean_b[0]), mb1 = __ldg(&mean_b[1]);
        const float cb0 = __ldg(&cov_b[0]),  cb1 = __ldg(&cov_b[1]);

        float lsum = 0.f, lsq = 0.f;
        #pragma unroll
        for (int p = 0; p < 2; ++p) {
            const float t = tanhf(acc[p][0] + mb);
            float pm0 = t * wm0, pm1 = t * wm1, pv0 = t * wc0, pv1 = t * wc1;
            #pragma unroll
            for (int off = 1; off <= 8; off <<= 1) {
                pm0 += __shfl_xor_sync(0xffffffffu, pm0, off);
                pm1 += __shfl_xor_sync(0xffffffffu, pm1, off);
                pv0 += __shfl_xor_sync(0xffffffffu, pv0, off);
                pv1 += __shfl_xor_sync(0xffffffffu, pv1, off);
            }
            if (lane == 0) {
                const int r = warp * 2 + p;
                moloc[r][0] = pm0 + mb0;  moloc[r][1] = pm1 + mb1;
                vloc[r][0]  = pv0 + cb0;  vloc[r][1]  = pv1 + cb1;
                const float v0 = pv0 + cb0, v1 = pv1 + cb1;
                lsum += v0 + v1;
                lsq  += v0 * v0 + v1 * v1;
            }
        }
        if (lane == 0) { ss[warp][0] = lsum; ss[warp][1] = lsq; }
    }
    __syncthreads();

    if (tid == 0) {
        float s = 0.f, q = 0.f;
        #pragma unroll
        for (int w = 0; w < 8; ++w) { s += ss[w][0]; q += ss[w][1]; }
        g_part[b][bx][0] = s;
        g_part[b][bx][1] = q;
    }

    // ---- Grid barrier (all 576 blocks resident: 4 blocks/SM x 148 >= 576) --
    if (tid == 0) {
        __threadfence();
        unsigned e0 = *((volatile unsigned*)&g_epoch);
        unsigned my = atomicAdd(&g_cnt, 1);
        if (my == NBLOCKS - 1) {
            atomicExch(&g_cnt, 0);
            __threadfence();
            atomicAdd(&g_epoch, 1);
        } else {
            while (*((volatile unsigned*)&g_epoch) == e0) { }
        }
        __threadfence();
    }
    __syncthreads();

    // ---- Phase B -----------------------------------------------------------
    if (tid < 32) {
        float s = 0.f, q = 0.f;
        for (int e = lane; e < BLOCKS_PER_BATCH; e += 32) {
            s += __ldcg(&g_part[b][e][0]);
            q += __ldcg(&g_part[b][e][1]);
        }
        #pragma unroll
        for (int off = 16; off; off >>= 1) {
            s += __shfl_xor_sync(0xffffffffu, s, off);
            q += __shfl_xor_sync(0xffffffffu, q, off);
        }
        const float n    = (float)(HW * 2);
        const float mu   = s / n;
        const float rstd = rsqrtf(q / n - mu * mu + 1e-5f);

        if (lane < ROWS) {
            const int i = i0 + lane;
            float v0 = (vloc[lane][0] - mu) * rstd;
            float v1 = (vloc[lane][1] - mu) * rstd;
            v0 = 5.f / (1.f + __expf(-v0)) + 0.05f;
            v1 = 5.f / (1.f + __expf(-v1)) + 0.05f;
            const float det   = v0 * v1;
            const float scale = 3.0f / (6.28f * sqrtf(det));
            const float m0 = (float)(i % 48) + moloc[lane][0];
            const float m1 = (float)(i / 48) + moloc[lane][1];
            prm[lane][0] = 1.f / v0;
            prm[lane][1] = 1.f / v1;
            prm[lane][2] = scale;
            prm[lane][3] = m0;
            prm[lane][4] = m1;
            out_mean[((long)b * HW + i) * 2 + 0] = m0;
            out_mean[((long)b * HW + i) * 2 + 1] = m1;
            out_det [(long)b * HW + i]           = det;
        }
    }
    __syncthreads();

    for (int t = tid; t < ROWS * 96; t += 288) {
        const int r = t / 96;
        const int k = t - r * 96;
        if (k < 48) {
            const float d = (float)k - prm[r][3];
            ex[r][k] = __expf(-0.5f * d * d * prm[r][0]) * prm[r][2];
        } else {
            const float d = (float)(k - 48) - prm[r][4];
            ey[r][k - 48] = __expf(-0.5f * d * d * prm[r][1]);
        }
    }
    __syncthreads();

    const int y0 = tid / 12;            // 0..23
    const int x0 = tid - y0 * 12;       // 0..11
    const int y1 = y0 + 24;             // 24..47
    float* dst_base = out_pdf + ((long)b * HW + i0) * HW;

    for (int it = 0; it < ROWS / 2; ++it) {             // 8 iterations
        if (it >= NSLOT) {
            if (tid == 0)
                asm volatile("cp.async.bulk.wait_group.read %0;" :: "n"(NSLOT - 1) : "memory");
            __syncthreads();
        }
        float4* buf = (float4*)ring[it & (NSLOT - 1)];
        #pragma unroll
        for (int rr = 0; rr < 2; ++rr) {
            const int r = 2 * it + rr;
            const float4 a = *(const float4*)&ex[r][x0 * 4];
            const float e0 = ey[r][y0];
            float4 v; v.x = a.x * e0; v.y = a.y * e0; v.z = a.z * e0; v.w = a.w * e0;
            buf[rr * 576 + tid] = v;
            const float e1 = ey[r][y1];
            float4 w; w.x = a.x * e1; w.y = a.y * e1; w.z = a.z * e1; w.w = a.w * e1;
            buf[rr * 576 + tid + 288] = w;
        }
        __syncthreads();
        if (tid == 0) {
            asm volatile("fence.proxy.async.shared::cta;" ::: "memory");
            unsigned int src;
            asm("{ .reg .u64 t; cvta.to.shared.u64 t, %1; cvt.u32.u64 %0, t; }"
                : "=r"(src) : "l"((float*)buf));
            float* dst = dst_base + (long)(2 * it) * HW;
            asm volatile(
                "cp.async.bulk.global.shared::cta.bulk_group [%0], [%1], %2;"
                :: "l"(dst), "r"(src), "r"((unsigned int)PAIR_BYTES) : "memory");
            asm volatile("cp.async.bulk.commit_group;" ::: "memory");
        }
    }
    if (tid == 0)
        asm volatile("cp.async.bulk.wait_group 0;" ::: "memory");
}

// ---------------------------------------------------------------------------
extern "C" void kernel_launch(void* const* d_in, const int* in_sizes, int n_in,
                              void* d_out, int out_size)
{
    const float* x      = (const float*)d_in[0];
    const float* map_w  = (const float*)d_in[1];
    const float* map_b  = (const float*)d_in[2];
    const float* mean_w = (const float*)d_in[3];
    const float* mean_b = (const float*)d_in[4];
    const float* cov_w  = (const float*)d_in[5];
    const float* cov_b  = (const float*)d_in[6];

    float* out      = (float*)d_out;
    float* out_pdf  = out;                                  // 4*2304*2304
    float* out_mean = out + (long)NB * HW * HW;             // 4*2304*2
    float* out_det  = out_mean + (long)NB * HW * 2;         // 4*2304

    dim3 g(BLOCKS_PER_BATCH, NB);
    fused<<<g, 288>>>(x, map_w, map_b, mean_w, mean_b, cov_w, cov_b,
                      out_pdf, out_mean, out_det);
}

// round 15
// speedup vs baseline: 1.1382x; 1.1382x over previous
#include <cuda_runtime.h>
#include <cuda_bf16.h>
#include <cstdint>

#define HW   2304
#define CIN  256
#define CMID 16
#define NB   4
#define K1_WARPS 4
#define PIX_PER_WARP 4
#define PIX_PER_BLOCK (K1_WARPS * PIX_PER_WARP)   // 16
#define BLOCKS_PER_BATCH (HW / PIX_PER_BLOCK)     // 144
#define ROWS_K3 16
#define ROW_BYTES (HW * 4)                        // 9216
#define RING 4

// Scratch (static device globals — no allocations allowed)
__device__ float g_v  [NB][HW][2];
__device__ float g_mo [NB][HW][2];
__device__ float g_part[NB][BLOCKS_PER_BATCH][2];

// ---------------------------------------------------------------------------
// Kernel 1: per-pixel 256->16 projection, tanh, 16->2 projections,
//           per-block partial sums. 4 pixels/warp, 128-thread blocks.
//           x loads use __ldcs (read-once; keep L2 free for pdf lines).
// ---------------------------------------------------------------------------
__global__ __launch_bounds__(128) void k1(
    const float* __restrict__ x,
    const float* __restrict__ map_w,  const float* __restrict__ map_b,
    const float* __restrict__ mean_w, const float* __restrict__ mean_b,
    const float* __restrict__ cov_w,  const float* __restrict__ cov_b)
{
    __shared__ float sw[CMID * CIN];        // 16 KB of weights
    const int b    = blockIdx.y;
    const int tid  = threadIdx.x;
    const int warp = tid >> 5;
    const int lane = tid & 31;

    {
        const float4* src = (const float4*)map_w;
        float4* dst = (float4*)sw;
        #pragma unroll
        for (int i = 0; i < 8; ++i) dst[tid + 128 * i] = src[tid + 128 * i];
    }
    __syncthreads();

    const int pix0 = (blockIdx.x * K1_WARPS + warp) * PIX_PER_WARP;
    const float* xb = x + ((long)b * HW + pix0) * CIN;

    float4 xv0[PIX_PER_WARP], xv1[PIX_PER_WARP];
    #pragma unroll
    for (int p = 0; p < PIX_PER_WARP; ++p) {
        const float4* row = (const float4*)(xb + p * CIN);
        xv0[p] = __ldcs(row + lane);
        xv1[p] = __ldcs(row + lane + 32);
    }

    float acc[PIX_PER_WARP][16];
    const float4* sw4 = (const float4*)sw;
    #pragma unroll
    for (int c = 0; c < CMID; ++c) {
        const float4 w0 = sw4[c * 64 + lane];
        const float4 w1 = sw4[c * 64 + 32 + lane];
        #pragma unroll
        for (int p = 0; p < PIX_PER_WARP; ++p) {
            float a;
            a = xv0[p].x * w0.x;
            a = fmaf(xv0[p].y, w0.y, a);
            a = fmaf(xv0[p].z, w0.z, a);
            a = fmaf(xv0[p].w, w0.w, a);
            a = fmaf(xv1[p].x, w1.x, a);
            a = fmaf(xv1[p].y, w1.y, a);
            a = fmaf(xv1[p].z, w1.z, a);
            a = fmaf(xv1[p].w, w1.w, a);
            acc[p][c] = a;
        }
    }

    // Halving butterfly: 16 values -> 1 per lane within each 16-lane half.
    #pragma unroll
    for (int st = 0; st < 4; ++st) {
        const int off = 1 << st;
        const bool up = (lane >> st) & 1;
        const int half = 8 >> st;
        #pragma unroll
        for (int p = 0; p < PIX_PER_WARP; ++p) {
            #pragma unroll
            for (int i = 0; i < 8; ++i) {
                if (i < half) {
                    float send  = up ? acc[p][i] : acc[p][i + half];
                    float other = __shfl_xor_sync(0xffffffffu, send, off);
                    float keep  = up ? acc[p][i + half] : acc[p][i];
                    acc[p][i] = keep + other;
                }
            }
        }
    }
    #pragma unroll
    for (int p = 0; p < PIX_PER_WARP; ++p)
        acc[p][0] += __shfl_xor_sync(0xffffffffu, acc[p][0], 16);

    // channel owned by this lane: bit-reverse of lane[3:0]
    const int ch = ((lane & 1) << 3) | ((lane & 2) << 1)
                 | ((lane & 4) >> 1) | ((lane & 8) >> 3);
    const float mb  = __ldg(&map_b[ch]);
    const float wm0 = __ldg(&mean_w[ch]);
    const float wm1 = __ldg(&mean_w[CMID + ch]);
    const float wc0 = __ldg(&cov_w[ch]);
    const float wc1 = __ldg(&cov_w[CMID + ch]);
    const float mb0 = __ldg(&mean_b[0]), mb1 = __ldg(&mean_b[1]);
    const float cb0 = __ldg(&cov_b[0]),  cb1 = __ldg(&cov_b[1]);

    float lsum = 0.f, lsq = 0.f;
    float mo0v[PIX_PER_WARP], mo1v[PIX_PER_WARP];
    float v0v[PIX_PER_WARP],  v1v[PIX_PER_WARP];
    #pragma unroll
    for (int p = 0; p < PIX_PER_WARP; ++p) {
        const float t = tanhf(acc[p][0] + mb);
        float pm0 = t * wm0, pm1 = t * wm1, pv0 = t * wc0, pv1 = t * wc1;
        #pragma unroll
        for (int off = 1; off <= 8; off <<= 1) {
            pm0 += __shfl_xor_sync(0xffffffffu, pm0, off);
            pm1 += __shfl_xor_sync(0xffffffffu, pm1, off);
            pv0 += __shfl_xor_sync(0xffffffffu, pv0, off);
            pv1 += __shfl_xor_sync(0xffffffffu, pv1, off);
        }
        mo0v[p] = pm0 + mb0;  mo1v[p] = pm1 + mb1;
        v0v[p]  = pv0 + cb0;  v1v[p]  = pv1 + cb1;
        lsum += v0v[p] + v1v[p];
        lsq  += v0v[p] * v0v[p] + v1v[p] * v1v[p];
    }

    if (lane == 0) {
        #pragma unroll
        for (int p = 0; p < PIX_PER_WARP; ++p) {
            g_mo[b][pix0 + p][0] = mo0v[p];
            g_mo[b][pix0 + p][1] = mo1v[p];
            g_v [b][pix0 + p][0] = v0v[p];
            g_v [b][pix0 + p][1] = v1v[p];
        }
    }

    __shared__ float ss[K1_WARPS][2];
    if (lane == 0) { ss[warp][0] = lsum; ss[warp][1] = lsq; }
    __syncthreads();
    if (tid == 0) {
        float s = 0.f, q = 0.f;
        #pragma unroll
        for (int w = 0; w < K1_WARPS; ++w) { s += ss[w][0]; q += ss[w][1]; }
        g_part[b][blockIdx.x][0] = s;
        g_part[b][blockIdx.x][1] = q;
    }
    // PDL: allow the dependent k3 launch to begin
    if (tid == 0) cudaTriggerProgrammaticLaunchCompletion();
}

// ---------------------------------------------------------------------------
// Kernel 3: pipelined TMA bulk stores. 288 threads, 16 rows/block,
// 4-deep ring of 9KB row buffers (exact R12 configuration).
// Launched with programmatic stream serialization; syncs on k1 before
// touching its outputs.
// ---------------------------------------------------------------------------
__global__ __launch_bounds__(288) void k3(float* __restrict__ out_pdf,
                                          float* __restrict__ out_mean,
                                          float* __restrict__ out_det)
{
    __shared__ __align__(16) float ring[RING][HW];      // 36 KB
    __shared__ __align__(16) float ex[ROWS_K3][48];     // 3 KB
    __shared__ float ey[ROWS_K3][48];                   // 3 KB
    __shared__ float prm[ROWS_K3][5];

    const int i0  = blockIdx.x * ROWS_K3;
    const int b   = blockIdx.y;
    const int tid = threadIdx.x;
    const int lane = tid & 31;

    // wait for k1's grid before consuming g_part/g_v/g_mo
    cudaGridDependencySynchronize();

    if (tid < 32) {
        float s = 0.f, q = 0.f;
        for (int e = lane; e < BLOCKS_PER_BATCH; e += 32) {
            s += g_part[b][e][0];
            q += g_part[b][e][1];
        }
        #pragma unroll
        for (int off = 16; off; off >>= 1) {
            s += __shfl_xor_sync(0xffffffffu, s, off);
            q += __shfl_xor_sync(0xffffffffu, q, off);
        }
        const float n    = (float)(HW * 2);
        const float mu   = s / n;
        const float rstd = rsqrtf(q / n - mu * mu + 1e-5f);

        if (lane < ROWS_K3) {
            const int i = i0 + lane;
            float v0 = (g_v[b][i][0] - mu) * rstd;
            float v1 = (g_v[b][i][1] - mu) * rstd;
            v0 = 5.f / (1.f + __expf(-v0)) + 0.05f;   // sigmoid*5 + 0.05
            v1 = 5.f / (1.f + __expf(-v1)) + 0.05f;
            const float det   = v0 * v1;
            const float scale = 3.0f / (6.28f * sqrtf(det));
            const float m0 = (float)(i % 48) + g_mo[b][i][0];
            const float m1 = (float)(i / 48) + g_mo[b][i][1];
            prm[lane][0] = 1.f / v0;
            prm[lane][1] = 1.f / v1;
            prm[lane][2] = scale;
            prm[lane][3] = m0;
            prm[lane][4] = m1;
            out_mean[((long)b * HW + i) * 2 + 0] = m0;
            out_mean[((long)b * HW + i) * 2 + 1] = m1;
            out_det [(long)b * HW + i]           = det;
        }
    }
    __syncthreads();

    // exp phase: 16 rows x 96 = 1536 slots over 288 threads
    for (int t = tid; t < ROWS_K3 * 96; t += 288) {
        const int r = t / 96;
        const int k = t - r * 96;
        if (k < 48) {
            const float d = (float)k - prm[r][3];
            ex[r][k] = __expf(-0.5f * d * d * prm[r][0]) * prm[r][2];
        } else {
            const float d = (float)(k - 48) - prm[r][4];
            ey[r][k - 48] = __expf(-0.5f * d * d * prm[r][1]);
        }
    }
    __syncthreads();

    // thread owns two float4 slots per row: j4 = tid and tid+288
    const int y0 = tid / 12;            // 0..23
    const int x0 = tid - y0 * 12;       // 0..11
    const int y1 = y0 + 24;             // 24..47
    float* dst_base = out_pdf + ((long)b * HW + i0) * HW;

    for (int r = 0; r < ROWS_K3; ++r) {
        if (r >= RING) {
            if (tid == 0)
                asm volatile("cp.async.bulk.wait_group.read %0;" :: "n"(RING - 1) : "memory");
            __syncthreads();
        }
        float4* buf = (float4*)ring[r & (RING - 1)];
        {
            const float e0 = ey[r][y0];
            const float4 a = *(const float4*)&ex[r][x0 * 4];
            float4 v; v.x = a.x * e0; v.y = a.y * e0; v.z = a.z * e0; v.w = a.w * e0;
            buf[tid] = v;
            const float e1 = ey[r][y1];
            float4 w; w.x = a.x * e1; w.y = a.y * e1; w.z = a.z * e1; w.w = a.w * e1;
            buf[tid + 288] = w;
        }
        __syncthreads();
        if (tid == 0) {
            asm volatile("fence.proxy.async.shared::cta;" ::: "memory");
            unsigned int src;
            asm("{ .reg .u64 t; cvta.to.shared.u64 t, %1; cvt.u32.u64 %0, t; }"
                : "=r"(src) : "l"((float*)buf));
            float* dst = dst_base + (long)r * HW;
            asm volatile(
                "cp.async.bulk.global.shared::cta.bulk_group [%0], [%1], %2;"
                :: "l"(dst), "r"(src), "r"((unsigned int)ROW_BYTES) : "memory");
            asm volatile("cp.async.bulk.commit_group;" ::: "memory");
        }
    }
    if (tid == 0)
        asm volatile("cp.async.bulk.wait_group 0;" ::: "memory");
}

// ---------------------------------------------------------------------------
extern "C" void kernel_launch(void* const* d_in, const int* in_sizes, int n_in,
                              void* d_out, int out_size)
{
    const float* x      = (const float*)d_in[0];
    const float* map_w  = (const float*)d_in[1];
    const float* map_b  = (const float*)d_in[2];
    const float* mean_w = (const float*)d_in[3];
    const float* mean_b = (const float*)d_in[4];
    const float* cov_w  = (const float*)d_in[5];
    const float* cov_b  = (const float*)d_in[6];

    float* out      = (float*)d_out;
    float* out_pdf  = out;                                  // 4*2304*2304
    float* out_mean = out + (long)NB * HW * HW;             // 4*2304*2
    float* out_det  = out_mean + (long)NB * HW * 2;         // 4*2304

    dim3 g1(BLOCKS_PER_BATCH, NB);
    k1<<<g1, 128>>>(x, map_w, map_b, mean_w, mean_b, cov_w, cov_b);

    // k3 with programmatic dependent launch (overlap launch + prologue)
    cudaLaunchConfig_t cfg = {};
    cfg.gridDim  = dim3(HW / ROWS_K3, NB);
    cfg.blockDim = dim3(288);
    cfg.dynamicSmemBytes = 0;
    cfg.stream = 0;
    cudaLaunchAttribute attrs[1];
    attrs[0].id = cudaLaunchAttributeProgrammaticStreamSerialization;
    attrs[0].val.programmaticStreamSerializationAllowed = 1;
    cfg.attrs = attrs;
    cfg.numAttrs = 1;
    cudaLaunchKernelEx(&cfg, k3, out_pdf, out_mean, out_det);
}